// round 1
// baseline (speedup 1.0000x reference)
#include <cuda_runtime.h>

#define NN 100000
#define EE 2500000
#define H  32

// Scratch (static __device__ — no allocation allowed)
__device__ int   g_degc[NN];
__device__ int   g_cur[NN];
__device__ int   g_off[NN + 1];
__device__ float g_dinv[NN];
__device__ float g_invdeg[NN];
__device__ int   g_csr_src[EE];
__device__ float g_csr_w[EE];
__device__ float g_x0[NN * H];
__device__ float g_x1[NN * H];

__global__ void zero_kernel() {
    int i = blockIdx.x * blockDim.x + threadIdx.x;
    if (i < NN) { g_degc[i] = 0; g_cur[i] = 0; }
}

__global__ void count_kernel(const int* __restrict__ ei) {
    int e = blockIdx.x * blockDim.x + threadIdx.x;
    if (e < EE) atomicAdd(&g_degc[ei[EE + e]], 1);
}

#define SCAN_T 1024
#define CHUNK  98   // ceil(100000/1024)
__global__ void scan_kernel() {
    __shared__ int s[SCAN_T];
    int t = threadIdx.x;
    int start = t * CHUNK;
    int end = min(start + CHUNK, NN);
    int sum = 0;
    for (int i = start; i < end; i++) sum += g_degc[i];
    s[t] = sum;
    __syncthreads();
    // Hillis-Steele inclusive scan
    for (int d = 1; d < SCAN_T; d <<= 1) {
        int v = (t >= d) ? s[t - d] : 0;
        __syncthreads();
        s[t] += v;
        __syncthreads();
    }
    int run = s[t] - sum;  // exclusive prefix
    for (int i = start; i < end; i++) {
        g_off[i] = run;
        int c = g_degc[i];
        run += c;
        float deg = 1.0f + (float)c;
        g_dinv[i]   = rsqrtf(deg);
        g_invdeg[i] = 1.0f / deg;
    }
    if (t == SCAN_T - 1) g_off[NN] = s[SCAN_T - 1];
}

__global__ void csr_kernel(const int* __restrict__ ei) {
    int e = blockIdx.x * blockDim.x + threadIdx.x;
    if (e >= EE) return;
    int s = ei[e];
    int d = ei[EE + e];
    int p = atomicAdd(&g_cur[d], 1);
    int i = g_off[d] + p;
    g_csr_src[i] = s;
    g_csr_w[i]   = g_dinv[s] * g_dinv[d];
}

__global__ void fc1_kernel(const float* __restrict__ x, const float* __restrict__ t,
                           const float* __restrict__ w, const float* __restrict__ b) {
    int i = blockIdx.x * blockDim.x + threadIdx.x;  // n*H + j
    if (i >= NN * H) return;
    int n = i >> 5, j = i & 31;
    float v = x[n] * w[j] + t[n] * w[H + j] + b[j];
    g_x0[i] = fmaxf(v, 0.0f);
}

// One conv layer. Aggregates RAW features (W commutes with segment_sum),
// then applies W via shuffles + shared memory, adds bias, relu.
// src_sel=0: x0 -> x1 ; src_sel=1: x1 -> x0
__global__ void conv_kernel(int src_sel,
                            const float* __restrict__ W, const float* __restrict__ b) {
    __shared__ float Ws[H * H];
    const float* __restrict__ Xin  = src_sel ? g_x1 : g_x0;
    float* __restrict__       Xout = src_sel ? g_x0 : g_x1;

    int tid = threadIdx.x;
    for (int i = tid; i < H * H; i += blockDim.x) Ws[i] = W[i];
    __syncthreads();

    int n    = (blockIdx.x * blockDim.x + tid) >> 5;
    int lane = tid & 31;
    if (n >= NN) return;

    int base = g_off[n];
    int end  = g_off[n + 1];

    // self-loop term: X[n] * (1/deg)
    float acc = Xin[n * H + lane] * g_invdeg[n];

    int e = base;
    for (; e + 4 <= end; e += 4) {
        int   s0 = g_csr_src[e],     s1 = g_csr_src[e + 1];
        int   s2 = g_csr_src[e + 2], s3 = g_csr_src[e + 3];
        float w0 = g_csr_w[e],       w1 = g_csr_w[e + 1];
        float w2 = g_csr_w[e + 2],   w3 = g_csr_w[e + 3];
        acc += Xin[s0 * H + lane] * w0;
        acc += Xin[s1 * H + lane] * w1;
        acc += Xin[s2 * H + lane] * w2;
        acc += Xin[s3 * H + lane] * w3;
    }
    for (; e < end; e++)
        acc += Xin[g_csr_src[e] * H + lane] * g_csr_w[e];

    // out[j] = relu( sum_k agg[k] * W[k][j] + b[j] ), j = lane
    float r = b[lane];
#pragma unroll
    for (int k = 0; k < H; k++)
        r += __shfl_sync(0xffffffffu, acc, k) * Ws[k * H + lane];

    Xout[n * H + lane] = fmaxf(r, 0.0f);
}

__global__ void fc3_kernel(const float* __restrict__ w, const float* __restrict__ b,
                           float* __restrict__ out) {
    int n    = (blockIdx.x * blockDim.x + threadIdx.x) >> 5;
    int lane = threadIdx.x & 31;
    if (n >= NN) return;
    float v = g_x1[n * H + lane] * w[lane];
#pragma unroll
    for (int d = 16; d > 0; d >>= 1) v += __shfl_down_sync(0xffffffffu, v, d);
    if (lane == 0) out[n] = v + b[0];
}

extern "C" void kernel_launch(void* const* d_in, const int* in_sizes, int n_in,
                              void* d_out, int out_size) {
    const float* x     = (const float*)d_in[0];
    const float* t     = (const float*)d_in[1];
    const int*   ei    = (const int*)d_in[2];
    const float* fc1_w = (const float*)d_in[3];
    const float* fc1_b = (const float*)d_in[4];
    const float* w1    = (const float*)d_in[5];
    const float* b1    = (const float*)d_in[6];
    const float* w2    = (const float*)d_in[7];
    const float* b2    = (const float*)d_in[8];
    const float* w3    = (const float*)d_in[9];
    const float* b3    = (const float*)d_in[10];
    const float* fc3_w = (const float*)d_in[11];
    const float* fc3_b = (const float*)d_in[12];
    float* out = (float*)d_out;

    zero_kernel<<<(NN + 255) / 256, 256>>>();
    count_kernel<<<(EE + 255) / 256, 256>>>(ei);
    scan_kernel<<<1, SCAN_T>>>();
    csr_kernel<<<(EE + 255) / 256, 256>>>(ei);
    fc1_kernel<<<(NN * H + 255) / 256, 256>>>(x, t, fc1_w, fc1_b);

    int cb = (NN * 32 + 255) / 256;  // warp per node
    conv_kernel<<<cb, 256>>>(0, w1, b1);
    conv_kernel<<<cb, 256>>>(1, w2, b2);
    conv_kernel<<<cb, 256>>>(0, w3, b3);
    fc3_kernel<<<cb, 256>>>(fc3_w, fc3_b, out);
}

// round 2
// speedup vs baseline: 1.9108x; 1.9108x over previous
#include <cuda_runtime.h>

#define NN 100000
#define EE 2500000
#define H  32
#define FULL 0xffffffffu

#define NB_SCAN ((NN + 255) / 256)   // 391

// Scratch (static __device__ — no allocation allowed)
__device__ int    g_degc[NN];
__device__ int    g_off[NN + 1];
__device__ int    g_bsum[NB_SCAN];
__device__ int    g_boff[NB_SCAN];
__device__ float  g_dinv[NN];
__device__ float  g_invdeg[NN];
__device__ int    g_pos[EE];
__device__ __align__(16) int2   g_csr[EE];
__device__ __align__(128) float g_x0[NN * H];
__device__ __align__(128) float g_x1[NN * H];
__device__ __align__(8)  float2 g_xt[NN];

// ---- prep: zero degree counters + pack (x,t) into float2 ----
__global__ void prep_kernel(const float* __restrict__ x, const float* __restrict__ t) {
    int i = blockIdx.x * blockDim.x + threadIdx.x;
    if (i < NN) {
        g_degc[i] = 0;
        g_xt[i] = make_float2(x[i], t[i]);
    }
}

// ---- count in-degree; remember each edge's slot within its bucket ----
__global__ void count_kernel(const int* __restrict__ ei) {
    int e = blockIdx.x * blockDim.x + threadIdx.x;
    if (e < EE) g_pos[e] = atomicAdd(&g_degc[ei[EE + e]], 1);
}

// ---- 3-phase parallel exclusive scan of g_degc ----
__global__ void scan_a_kernel() {   // block partial sums
    __shared__ int ws[8];
    int n = blockIdx.x * 256 + threadIdx.x;
    int c = (n < NN) ? g_degc[n] : 0;
    int v = c;
#pragma unroll
    for (int d = 1; d < 32; d <<= 1) { int u = __shfl_up_sync(FULL, v, d); if ((threadIdx.x & 31) >= d) v += u; }
    if ((threadIdx.x & 31) == 31) ws[threadIdx.x >> 5] = v;
    __syncthreads();
    if (threadIdx.x == 0) {
        int s = 0;
#pragma unroll
        for (int i = 0; i < 8; i++) s += ws[i];
        g_bsum[blockIdx.x] = s;
    }
}

__global__ void scan_b_kernel() {   // scan 391 block sums (1 block, 512 thr)
    __shared__ int s[512];
    int t = threadIdx.x;
    int v = (t < NB_SCAN) ? g_bsum[t] : 0;
    s[t] = v;
    __syncthreads();
    for (int d = 1; d < 512; d <<= 1) {
        int u = (t >= d) ? s[t - d] : 0;
        __syncthreads();
        s[t] += u;
        __syncthreads();
    }
    if (t < NB_SCAN) g_boff[t] = s[t] - v;   // exclusive
}

__global__ void scan_c_kernel() {   // block-local exclusive scan + finalize
    __shared__ int ws[8];
    int n = blockIdx.x * 256 + threadIdx.x;
    int lane = threadIdx.x & 31, wid = threadIdx.x >> 5;
    int c = (n < NN) ? g_degc[n] : 0;
    int v = c;
#pragma unroll
    for (int d = 1; d < 32; d <<= 1) { int u = __shfl_up_sync(FULL, v, d); if (lane >= d) v += u; }
    if (lane == 31) ws[wid] = v;
    __syncthreads();
    if (threadIdx.x == 0) {
        int run = 0;
#pragma unroll
        for (int i = 0; i < 8; i++) { int t = ws[i]; ws[i] = run; run += t; }
    }
    __syncthreads();
    if (n < NN) {
        int excl = (v - c) + ws[wid] + g_boff[blockIdx.x];
        g_off[n] = excl;
        float deg = 1.0f + (float)c;
        g_dinv[n]   = rsqrtf(deg);
        g_invdeg[n] = 1.0f / deg;
        if (n == NN - 1) g_off[NN] = excl + c;
    }
}

// ---- scatter edges into CSR (atomic-free), weight precomputed ----
__global__ void csr_kernel(const int* __restrict__ ei) {
    int e = blockIdx.x * blockDim.x + threadIdx.x;
    if (e >= EE) return;
    int s = ei[e];
    int d = ei[EE + e];
    int i = g_off[d] + g_pos[e];
    float w = g_dinv[s] * g_dinv[d];
    g_csr[i] = make_int2(s, __float_as_int(w));
}

// ---- conv layer 1: features recomputed on the fly from (x,t) ----
__global__ __launch_bounds__(256) void conv1_kernel(const float* __restrict__ Fw,
                                                    const float* __restrict__ Fb,
                                                    const float* __restrict__ W,
                                                    const float* __restrict__ b) {
    __shared__ float Ws[H * H];
    int tid = threadIdx.x;
    for (int i = tid; i < H * H; i += blockDim.x) Ws[i] = W[i];
    __syncthreads();

    int n    = (blockIdx.x * blockDim.x + tid) >> 5;
    int lane = tid & 31;
    if (n >= NN) return;

    float fw0 = Fw[lane], fw1 = Fw[H + lane], fb = Fb[lane];

    int base = g_off[n], cnt = g_off[n + 1] - base;
    const int2* __restrict__ ep = g_csr + base;

    float2 xtn = g_xt[n];
    float acc = fmaxf(fmaf(xtn.x, fw0, fmaf(xtn.y, fw1, fb)), 0.0f) * g_invdeg[n];

    int e = 0;
    for (; e + 4 <= cnt; e += 4) {
        int2 a = ep[e], b2 = ep[e + 1], c = ep[e + 2], d = ep[e + 3];
        float2 pa = g_xt[a.x], pb = g_xt[b2.x], pc = g_xt[c.x], pd = g_xt[d.x];
        acc = fmaf(fmaxf(fmaf(pa.x, fw0, fmaf(pa.y, fw1, fb)), 0.0f), __int_as_float(a.y),  acc);
        acc = fmaf(fmaxf(fmaf(pb.x, fw0, fmaf(pb.y, fw1, fb)), 0.0f), __int_as_float(b2.y), acc);
        acc = fmaf(fmaxf(fmaf(pc.x, fw0, fmaf(pc.y, fw1, fb)), 0.0f), __int_as_float(c.y),  acc);
        acc = fmaf(fmaxf(fmaf(pd.x, fw0, fmaf(pd.y, fw1, fb)), 0.0f), __int_as_float(d.y),  acc);
    }
    for (; e < cnt; e++) {
        int2 a = ep[e];
        float2 pa = g_xt[a.x];
        acc = fmaf(fmaxf(fmaf(pa.x, fw0, fmaf(pa.y, fw1, fb)), 0.0f), __int_as_float(a.y), acc);
    }

    float r = b[lane];
#pragma unroll
    for (int k = 0; k < H; k++)
        r = fmaf(__shfl_sync(FULL, acc, k), Ws[k * H + lane], r);
    g_x1[n * H + lane] = fmaxf(r, 0.0f);
}

// ---- conv layer 2: g_x1 -> g_x0 ----
__global__ __launch_bounds__(256) void conv2_kernel(const float* __restrict__ W,
                                                    const float* __restrict__ b) {
    __shared__ float Ws[H * H];
    int tid = threadIdx.x;
    for (int i = tid; i < H * H; i += blockDim.x) Ws[i] = W[i];
    __syncthreads();

    int n    = (blockIdx.x * blockDim.x + tid) >> 5;
    int lane = tid & 31;
    if (n >= NN) return;

    int base = g_off[n], cnt = g_off[n + 1] - base;
    const int2* __restrict__ ep = g_csr + base;
    const float* __restrict__ Xin = g_x1;

    float acc = Xin[n * H + lane] * g_invdeg[n];
    int e = 0;
    for (; e + 4 <= cnt; e += 4) {
        int2 a = ep[e], b2 = ep[e + 1], c = ep[e + 2], d = ep[e + 3];
        acc = fmaf(Xin[a.x  * H + lane], __int_as_float(a.y),  acc);
        acc = fmaf(Xin[b2.x * H + lane], __int_as_float(b2.y), acc);
        acc = fmaf(Xin[c.x  * H + lane], __int_as_float(c.y),  acc);
        acc = fmaf(Xin[d.x  * H + lane], __int_as_float(d.y),  acc);
    }
    for (; e < cnt; e++) {
        int2 a = ep[e];
        acc = fmaf(Xin[a.x * H + lane], __int_as_float(a.y), acc);
    }

    float r = b[lane];
#pragma unroll
    for (int k = 0; k < H; k++)
        r = fmaf(__shfl_sync(FULL, acc, k), Ws[k * H + lane], r);
    g_x0[n * H + lane] = fmaxf(r, 0.0f);
}

// ---- conv layer 3 fused with fc3: g_x0 -> out ----
__global__ __launch_bounds__(256) void conv3_kernel(const float* __restrict__ W,
                                                    const float* __restrict__ b,
                                                    const float* __restrict__ f3w,
                                                    const float* __restrict__ f3b,
                                                    float* __restrict__ out) {
    __shared__ float Ws[H * H];
    int tid = threadIdx.x;
    for (int i = tid; i < H * H; i += blockDim.x) Ws[i] = W[i];
    __syncthreads();

    int n    = (blockIdx.x * blockDim.x + tid) >> 5;
    int lane = tid & 31;
    if (n >= NN) return;

    int base = g_off[n], cnt = g_off[n + 1] - base;
    const int2* __restrict__ ep = g_csr + base;
    const float* __restrict__ Xin = g_x0;

    float acc = Xin[n * H + lane] * g_invdeg[n];
    int e = 0;
    for (; e + 4 <= cnt; e += 4) {
        int2 a = ep[e], b2 = ep[e + 1], c = ep[e + 2], d = ep[e + 3];
        acc = fmaf(Xin[a.x  * H + lane], __int_as_float(a.y),  acc);
        acc = fmaf(Xin[b2.x * H + lane], __int_as_float(b2.y), acc);
        acc = fmaf(Xin[c.x  * H + lane], __int_as_float(c.y),  acc);
        acc = fmaf(Xin[d.x  * H + lane], __int_as_float(d.y),  acc);
    }
    for (; e < cnt; e++) {
        int2 a = ep[e];
        acc = fmaf(Xin[a.x * H + lane], __int_as_float(a.y), acc);
    }

    float r = b[lane];
#pragma unroll
    for (int k = 0; k < H; k++)
        r = fmaf(__shfl_sync(FULL, acc, k), Ws[k * H + lane], r);

    float v = fmaxf(r, 0.0f) * f3w[lane];
#pragma unroll
    for (int d = 16; d > 0; d >>= 1) v += __shfl_down_sync(FULL, v, d);
    if (lane == 0) out[n] = v + f3b[0];
}

extern "C" void kernel_launch(void* const* d_in, const int* in_sizes, int n_in,
                              void* d_out, int out_size) {
    const float* x     = (const float*)d_in[0];
    const float* t     = (const float*)d_in[1];
    const int*   ei    = (const int*)d_in[2];
    const float* fc1_w = (const float*)d_in[3];
    const float* fc1_b = (const float*)d_in[4];
    const float* w1    = (const float*)d_in[5];
    const float* b1    = (const float*)d_in[6];
    const float* w2    = (const float*)d_in[7];
    const float* b2    = (const float*)d_in[8];
    const float* w3    = (const float*)d_in[9];
    const float* b3    = (const float*)d_in[10];
    const float* fc3_w = (const float*)d_in[11];
    const float* fc3_b = (const float*)d_in[12];
    float* out = (float*)d_out;

    prep_kernel<<<NB_SCAN, 256>>>(x, t);
    count_kernel<<<(EE + 255) / 256, 256>>>(ei);
    scan_a_kernel<<<NB_SCAN, 256>>>();
    scan_b_kernel<<<1, 512>>>();
    scan_c_kernel<<<NB_SCAN, 256>>>();
    csr_kernel<<<(EE + 255) / 256, 256>>>(ei);

    int cb = (NN * 32 + 255) / 256;  // warp per node
    conv1_kernel<<<cb, 256>>>(fc1_w, fc1_b, w1, b1);
    conv2_kernel<<<cb, 256>>>(w2, b2);
    conv3_kernel<<<cb, 256>>>(w3, b3, fc3_w, fc3_b, out);
}

// round 3
// speedup vs baseline: 2.1282x; 1.1138x over previous
#include <cuda_runtime.h>

#define NN 100000
#define EE 2500000
#define H  32
#define FULL 0xffffffffu

#define NB ((NN + 255) / 256)        // 391 scan blocks
#define PE_MAX (EE + 3 * NN + 4)     // padded CSR upper bound

// Scratch (static __device__ — zero-initialized at load; rows NN stay zero forever)
__device__ int            g_degc[NN];
__device__ int            g_off[NN + 1];
__device__ int            g_bsum[NB];
__device__ int            g_boff[NB];
__device__ float          g_dinv[NN];
__device__ unsigned short g_pos[EE];
__device__ __align__(16)  int    g_csr[PE_MAX];
__device__ __align__(16)  float4 g_xtd[NN + 1];        // (x, t, dinv, 0); row NN = zeros
__device__ __align__(128) float  g_x0[(NN + 1) * H];   // scaled features; row NN = zeros
__device__ __align__(128) float  g_x1[(NN + 1) * H];

// ---- prep: zero degree counters + pack (x,t) ----
__global__ void prep_kernel(const float* __restrict__ x, const float* __restrict__ t) {
    int i = blockIdx.x * blockDim.x + threadIdx.x;
    if (i < NN) {
        g_degc[i] = 0;
        g_xtd[i] = make_float4(x[i], t[i], 0.0f, 0.0f);
    }
}

// ---- count in-degree; remember each edge's rank within its bucket ----
__global__ void count_kernel(const int* __restrict__ ei) {
    int e = blockIdx.x * blockDim.x + threadIdx.x;
    if (e < EE) g_pos[e] = (unsigned short)atomicAdd(&g_degc[ei[EE + e]], 1);
}

// ---- 3-phase exclusive scan of PADDED degrees ----
__global__ void scan_a_kernel() {   // block partial sums of padded degrees
    __shared__ int ws[8];
    int n = blockIdx.x * 256 + threadIdx.x;
    int lane = threadIdx.x & 31, wid = threadIdx.x >> 5;
    int c = (n < NN) ? g_degc[n] : 0;
    int v = (c + 3) & ~3;
#pragma unroll
    for (int d = 16; d > 0; d >>= 1) v += __shfl_down_sync(FULL, v, d);
    if (lane == 0) ws[wid] = v;
    __syncthreads();
    if (threadIdx.x == 0) {
        int s = 0;
#pragma unroll
        for (int i = 0; i < 8; i++) s += ws[i];
        g_bsum[blockIdx.x] = s;
    }
}

__global__ void scan_b_kernel() {   // scan 391 block sums (1 block, 512 thr, shuffle-based)
    __shared__ int ws[16];
    int t = threadIdx.x, lane = t & 31, wid = t >> 5;
    int v = (t < NB) ? g_bsum[t] : 0;
    int inc = v;
#pragma unroll
    for (int d = 1; d < 32; d <<= 1) { int u = __shfl_up_sync(FULL, inc, d); if (lane >= d) inc += u; }
    if (lane == 31) ws[wid] = inc;
    __syncthreads();
    if (wid == 0) {
        int s = (lane < 16) ? ws[lane] : 0;
        int si = s;
#pragma unroll
        for (int d = 1; d < 16; d <<= 1) { int u = __shfl_up_sync(FULL, si, d); if (lane >= d) si += u; }
        if (lane < 16) ws[lane] = si - s;   // exclusive warp offsets
    }
    __syncthreads();
    if (t < NB) g_boff[t] = inc - v + ws[wid];
}

__global__ void scan_c_kernel() {   // finalize offsets, dinv, and CSR pad fill
    __shared__ int ws[8];
    int n = blockIdx.x * 256 + threadIdx.x;
    int lane = threadIdx.x & 31, wid = threadIdx.x >> 5;
    int c  = (n < NN) ? g_degc[n] : 0;
    int pc = (c + 3) & ~3;
    int v = pc;
#pragma unroll
    for (int d = 1; d < 32; d <<= 1) { int u = __shfl_up_sync(FULL, v, d); if (lane >= d) v += u; }
    if (lane == 31) ws[wid] = v;
    __syncthreads();
    if (threadIdx.x == 0) {
        int run = 0;
#pragma unroll
        for (int i = 0; i < 8; i++) { int tv = ws[i]; ws[i] = run; run += tv; }
    }
    __syncthreads();
    if (n < NN) {
        int excl = (v - pc) + ws[wid] + g_boff[blockIdx.x];
        g_off[n] = excl;
        float dinv = rsqrtf(1.0f + (float)c);
        g_dinv[n] = dinv;
        ((float*)g_xtd)[4 * n + 2] = dinv;          // xtd.z = dinv
        for (int i = excl + c; i < excl + pc; i++)  // pad slots -> zero row
            g_csr[i] = NN;
        if (n == NN - 1) g_off[NN] = excl + pc;
    }
}

// ---- scatter src indices into padded CSR (atomic-free) ----
__global__ void csr_kernel(const int* __restrict__ ei) {
    int e = blockIdx.x * blockDim.x + threadIdx.x;
    if (e >= EE) return;
    int s = ei[e];
    int d = ei[EE + e];
    g_csr[g_off[d] + (int)g_pos[e]] = s;
}

// ---- conv layer 1: fc1 features (incl. dinv scale) recomputed per gather ----
__global__ __launch_bounds__(256) void conv1_kernel(const float* __restrict__ Fw,
                                                    const float* __restrict__ Fb,
                                                    const float* __restrict__ W,
                                                    const float* __restrict__ b) {
    __shared__ float Ws[H * H];
    int tid = threadIdx.x;
    for (int i = tid; i < H * H; i += blockDim.x) Ws[i] = W[i];
    __syncthreads();

    int n    = (blockIdx.x * blockDim.x + tid) >> 5;
    int lane = tid & 31;
    if (n >= NN) return;

    float fw0 = Fw[lane], fw1 = Fw[H + lane], fb = Fb[lane];

    int off = g_off[n];
    int nq  = (g_off[n + 1] - off) >> 2;
    const int4* __restrict__ ep = (const int4*)g_csr + (off >> 2);

    float4 p = g_xtd[n];   // p.z = dinv[n]
    float acc = fmaxf(fmaf(p.x, fw0, fmaf(p.y, fw1, fb)), 0.0f) * p.z;  // self (Xs[n])

    int q = 0;
    for (; q + 2 <= nq; q += 2) {
        int4 a = ep[q], b4 = ep[q + 1];
        float4 A = g_xtd[a.x],  B = g_xtd[a.y],  C = g_xtd[a.z],  D = g_xtd[a.w];
        float4 E = g_xtd[b4.x], F = g_xtd[b4.y], G = g_xtd[b4.z], I = g_xtd[b4.w];
        acc += fmaxf(fmaf(A.x, fw0, fmaf(A.y, fw1, fb)), 0.0f) * A.z;
        acc += fmaxf(fmaf(B.x, fw0, fmaf(B.y, fw1, fb)), 0.0f) * B.z;
        acc += fmaxf(fmaf(C.x, fw0, fmaf(C.y, fw1, fb)), 0.0f) * C.z;
        acc += fmaxf(fmaf(D.x, fw0, fmaf(D.y, fw1, fb)), 0.0f) * D.z;
        acc += fmaxf(fmaf(E.x, fw0, fmaf(E.y, fw1, fb)), 0.0f) * E.z;
        acc += fmaxf(fmaf(F.x, fw0, fmaf(F.y, fw1, fb)), 0.0f) * F.z;
        acc += fmaxf(fmaf(G.x, fw0, fmaf(G.y, fw1, fb)), 0.0f) * G.z;
        acc += fmaxf(fmaf(I.x, fw0, fmaf(I.y, fw1, fb)), 0.0f) * I.z;
    }
    if (q < nq) {
        int4 a = ep[q];
        float4 A = g_xtd[a.x], B = g_xtd[a.y], C = g_xtd[a.z], D = g_xtd[a.w];
        acc += fmaxf(fmaf(A.x, fw0, fmaf(A.y, fw1, fb)), 0.0f) * A.z;
        acc += fmaxf(fmaf(B.x, fw0, fmaf(B.y, fw1, fb)), 0.0f) * B.z;
        acc += fmaxf(fmaf(C.x, fw0, fmaf(C.y, fw1, fb)), 0.0f) * C.z;
        acc += fmaxf(fmaf(D.x, fw0, fmaf(D.y, fw1, fb)), 0.0f) * D.z;
    }

    float a2 = acc * p.z;    // dinv[n] * (self + neighbor sum)
    float r = b[lane];
#pragma unroll
    for (int k = 0; k < H; k++)
        r = fmaf(__shfl_sync(FULL, a2, k), Ws[k * H + lane], r);
    g_x1[n * H + lane] = fmaxf(r, 0.0f) * p.z;   // write scaled feature Xs
}

// ---- conv layer 2: g_x1 (scaled) -> g_x0 (scaled) ----
__global__ __launch_bounds__(256) void conv2_kernel(const float* __restrict__ W,
                                                    const float* __restrict__ b) {
    __shared__ float Ws[H * H];
    int tid = threadIdx.x;
    for (int i = tid; i < H * H; i += blockDim.x) Ws[i] = W[i];
    __syncthreads();

    int n    = (blockIdx.x * blockDim.x + tid) >> 5;
    int lane = tid & 31;
    if (n >= NN) return;

    int off = g_off[n];
    int nq  = (g_off[n + 1] - off) >> 2;
    const int4* __restrict__ ep = (const int4*)g_csr + (off >> 2);
    const float* __restrict__ Xin = g_x1;

    float acc = Xin[n * H + lane];   // self
    int q = 0;
    for (; q + 2 <= nq; q += 2) {
        int4 a = ep[q], b4 = ep[q + 1];
        float v0 = Xin[a.x  * H + lane], v1 = Xin[a.y  * H + lane];
        float v2 = Xin[a.z  * H + lane], v3 = Xin[a.w  * H + lane];
        float v4 = Xin[b4.x * H + lane], v5 = Xin[b4.y * H + lane];
        float v6 = Xin[b4.z * H + lane], v7 = Xin[b4.w * H + lane];
        acc += ((v0 + v1) + (v2 + v3)) + ((v4 + v5) + (v6 + v7));
    }
    if (q < nq) {
        int4 a = ep[q];
        acc += ((Xin[a.x * H + lane] + Xin[a.y * H + lane]) +
                (Xin[a.z * H + lane] + Xin[a.w * H + lane]));
    }

    float dn = g_dinv[n];
    float a2 = acc * dn;
    float r = b[lane];
#pragma unroll
    for (int k = 0; k < H; k++)
        r = fmaf(__shfl_sync(FULL, a2, k), Ws[k * H + lane], r);
    g_x0[n * H + lane] = fmaxf(r, 0.0f) * dn;
}

// ---- conv layer 3 fused with fc3: g_x0 (scaled) -> out ----
__global__ __launch_bounds__(256) void conv3_kernel(const float* __restrict__ W,
                                                    const float* __restrict__ b,
                                                    const float* __restrict__ f3w,
                                                    const float* __restrict__ f3b,
                                                    float* __restrict__ out) {
    __shared__ float Ws[H * H];
    int tid = threadIdx.x;
    for (int i = tid; i < H * H; i += blockDim.x) Ws[i] = W[i];
    __syncthreads();

    int n    = (blockIdx.x * blockDim.x + tid) >> 5;
    int lane = tid & 31;
    if (n >= NN) return;

    int off = g_off[n];
    int nq  = (g_off[n + 1] - off) >> 2;
    const int4* __restrict__ ep = (const int4*)g_csr + (off >> 2);
    const float* __restrict__ Xin = g_x0;

    float acc = Xin[n * H + lane];
    int q = 0;
    for (; q + 2 <= nq; q += 2) {
        int4 a = ep[q], b4 = ep[q + 1];
        float v0 = Xin[a.x  * H + lane], v1 = Xin[a.y  * H + lane];
        float v2 = Xin[a.z  * H + lane], v3 = Xin[a.w  * H + lane];
        float v4 = Xin[b4.x * H + lane], v5 = Xin[b4.y * H + lane];
        float v6 = Xin[b4.z * H + lane], v7 = Xin[b4.w * H + lane];
        acc += ((v0 + v1) + (v2 + v3)) + ((v4 + v5) + (v6 + v7));
    }
    if (q < nq) {
        int4 a = ep[q];
        acc += ((Xin[a.x * H + lane] + Xin[a.y * H + lane]) +
                (Xin[a.z * H + lane] + Xin[a.w * H + lane]));
    }

    float a2 = acc * g_dinv[n];
    float r = b[lane];
#pragma unroll
    for (int k = 0; k < H; k++)
        r = fmaf(__shfl_sync(FULL, a2, k), Ws[k * H + lane], r);

    float v = fmaxf(r, 0.0f) * f3w[lane];   // final layer: NOT scaled
#pragma unroll
    for (int d = 16; d > 0; d >>= 1) v += __shfl_down_sync(FULL, v, d);
    if (lane == 0) out[n] = v + f3b[0];
}

extern "C" void kernel_launch(void* const* d_in, const int* in_sizes, int n_in,
                              void* d_out, int out_size) {
    const float* x     = (const float*)d_in[0];
    const float* t     = (const float*)d_in[1];
    const int*   ei    = (const int*)d_in[2];
    const float* fc1_w = (const float*)d_in[3];
    const float* fc1_b = (const float*)d_in[4];
    const float* w1    = (const float*)d_in[5];
    const float* b1    = (const float*)d_in[6];
    const float* w2    = (const float*)d_in[7];
    const float* b2    = (const float*)d_in[8];
    const float* w3    = (const float*)d_in[9];
    const float* b3    = (const float*)d_in[10];
    const float* fc3_w = (const float*)d_in[11];
    const float* fc3_b = (const float*)d_in[12];
    float* out = (float*)d_out;

    prep_kernel<<<NB, 256>>>(x, t);
    count_kernel<<<(EE + 255) / 256, 256>>>(ei);
    scan_a_kernel<<<NB, 256>>>();
    scan_b_kernel<<<1, 512>>>();
    scan_c_kernel<<<NB, 256>>>();
    csr_kernel<<<(EE + 255) / 256, 256>>>(ei);

    int cb = (NN * 32 + 255) / 256;  // warp per node
    conv1_kernel<<<cb, 256>>>(fc1_w, fc1_b, w1, b1);
    conv2_kernel<<<cb, 256>>>(w2, b2);
    conv3_kernel<<<cb, 256>>>(w3, b3, fc3_w, fc3_b, out);
}